// round 1
// baseline (speedup 1.0000x reference)
#include <cuda_runtime.h>

// MSAColumnGlobalAttention, B=1 S=2048 R=384 D=64 H=8 C=8
// One CTA per residue r. Two passes over the sequence axis with LN recompute.

namespace {
constexpr int S_LEN  = 2048;
constexpr int R_LEN  = 384;
constexpr int DDIM   = 64;
constexpr int TILE   = 128;
constexpr int NTILES = S_LEN / TILE;   // 16
constexpr int XST    = 66;             // padded row stride (floats), even for float2
constexpr int NTHR   = 1024;

// shared-memory layout (float offsets)
constexpr int OFF_KVT  = 0;                      // kvT[16][2048]; rawbuf aliases (pass 2)
constexpr int OFF_XBUF = 16 * S_LEN;             // xbuf[128][66]
constexpr int OFF_MASK = OFF_XBUF + TILE * XST;  // mask[2048]
constexpr int OFF_WKV  = OFF_MASK + S_LEN;       // Wkv[64][16]
constexpr int OFF_WG   = OFF_WKV + 64 * 16;      // Wg[64][64]
constexpr int OFF_WOP  = OFF_WG + 64 * 64;       // o-scaled Wo[64][64]
constexpr int OFF_LNG  = OFF_WOP + 64 * 64;
constexpr int OFF_LNB  = OFF_LNG + 64;
constexpr int OFF_BG   = OFF_LNB + 64;
constexpr int OFF_BO   = OFF_BG + 64;
constexpr int OFF_QN   = OFF_BO + 64;            // q numerator [64]
constexpr int OFF_QS   = OFF_QN + 64;            // q vector [64]
constexpr int OFF_OSV  = OFF_QS + 64;            // o vector [64]
constexpr int OFF_RED  = OFF_OSV + 64;           // softmax scratch [320]
constexpr int OFF_MS   = OFF_RED + 320;          // mask sum
constexpr int SMEM_FLOATS = OFF_MS + 4;
constexpr size_t SMEM_BYTES = (size_t)SMEM_FLOATS * sizeof(float);
}  // namespace

__device__ __forceinline__ unsigned long long pk2(float x, float y) {
    unsigned long long r;
    asm("mov.b64 %0,{%1,%2};" : "=l"(r) : "f"(x), "f"(y));
    return r;
}
__device__ __forceinline__ float2 up2(unsigned long long a) {
    float2 r;
    asm("mov.b64 {%0,%1},%2;" : "=f"(r.x), "=f"(r.y) : "l"(a));
    return r;
}
__device__ __forceinline__ unsigned long long fma2(unsigned long long a,
                                                   unsigned long long b,
                                                   unsigned long long c) {
    unsigned long long d;
    asm("fma.rn.f32x2 %0,%1,%2,%3;" : "=l"(d) : "l"(a), "l"(b), "l"(c));
    return d;
}

__global__ __launch_bounds__(NTHR, 1)
void msa_col_attn(const float* __restrict__ M_raw, const float* __restrict__ M_mask,
                  const float* __restrict__ ln_g, const float* __restrict__ ln_b,
                  const float* __restrict__ Wq, const float* __restrict__ Wk,
                  const float* __restrict__ Wv, const float* __restrict__ Wg,
                  const float* __restrict__ bg, const float* __restrict__ Wo,
                  const float* __restrict__ bo, float* __restrict__ outp)
{
    extern __shared__ float sm[];
    float* kvT  = sm + OFF_KVT;
    float* rawb = sm + OFF_KVT;   // alias: only used in pass 2 (kvT dead then)
    float* xb   = sm + OFF_XBUF;
    float* mkb  = sm + OFF_MASK;
    float* wkv  = sm + OFF_WKV;
    float* wgs  = sm + OFF_WG;
    float* wop  = sm + OFF_WOP;
    float* lng  = sm + OFF_LNG;
    float* lnbs = sm + OFF_LNB;
    float* bgs  = sm + OFF_BG;
    float* bos  = sm + OFF_BO;
    float* qn   = sm + OFF_QN;
    float* qsv  = sm + OFF_QS;
    float* osv  = sm + OFF_OSV;
    float* red  = sm + OFF_RED;
    float* msp  = sm + OFF_MS;

    const int r    = blockIdx.x;
    const int tid  = threadIdx.x;
    const int lane = tid & 31;
    const int warp = tid >> 5;
    const int d0   = lane << 1;

    // ---- stage weights ----
    for (int i = tid; i < 64 * 64; i += NTHR) wgs[i] = Wg[i];
    for (int i = tid; i < 64 * 8; i += NTHR) {
        int d = i >> 3, c = i & 7;
        wkv[d * 16 + c]     = Wk[i];
        wkv[d * 16 + 8 + c] = Wv[i];
    }
    if (tid < 64) {
        lng[tid] = ln_g[tid]; lnbs[tid] = ln_b[tid];
        bgs[tid] = bg[tid];   bos[tid]  = bo[tid];
    }
    __syncthreads();

    // ================= PASS 1: LN, k/v, masked q accumulation =================
    float qn0 = 0.f, qn1 = 0.f, msl = 0.f;

    for (int t = 0; t < NTILES; ++t) {
        #pragma unroll
        for (int k = 0; k < 4; ++k) {
            const int sl = warp + 32 * k;           // 0..127
            const int s  = t * TILE + sl;
            const float2 xin = *reinterpret_cast<const float2*>(
                M_raw + ((size_t)s * R_LEN + r) * DDIM + d0);
            float sum = xin.x + xin.y;
            float sq  = xin.x * xin.x + xin.y * xin.y;
            #pragma unroll
            for (int o = 16; o > 0; o >>= 1) {
                sum += __shfl_xor_sync(0xffffffffu, sum, o);
                sq  += __shfl_xor_sync(0xffffffffu, sq, o);
            }
            const float mu  = sum * (1.f / 64.f);
            const float var = fmaf(-mu, mu, sq * (1.f / 64.f));
            const float inv = rsqrtf(var + 1e-5f);
            const float xh0 = fmaf((xin.x - mu) * inv, lng[d0],     lnbs[d0]);
            const float xh1 = fmaf((xin.y - mu) * inv, lng[d0 + 1], lnbs[d0 + 1]);
            float m = (lane == 0) ? M_mask[(size_t)s * R_LEN + r] : 0.f;
            m = __shfl_sync(0xffffffffu, m, 0);
            if (lane == 0) { mkb[s] = m; msl += m; }
            qn0 = fmaf(m, xh0, qn0);
            qn1 = fmaf(m, xh1, qn1);
            *reinterpret_cast<float2*>(xb + sl * XST + d0) = make_float2(xh0, xh1);
        }
        __syncthreads();
        {   // k/v GEMM for the tile, writes transposed kvT[c][s]
            const int sl = tid >> 3, cg = tid & 7;
            const float* xr = xb + sl * XST;
            unsigned long long acc = 0ull;
            #pragma unroll 8
            for (int d = 0; d < 64; ++d) {
                const float x = xr[d];
                const unsigned long long w2 =
                    *reinterpret_cast<const unsigned long long*>(wkv + d * 16 + cg * 2);
                acc = fma2(pk2(x, x), w2, acc);
            }
            const float2 a = up2(acc);
            const int s = t * TILE + sl;
            kvT[(2 * cg) * S_LEN + s]     = a.x;
            kvT[(2 * cg + 1) * S_LEN + s] = a.y;
        }
        __syncthreads();
    }

    // ---- deterministic cross-warp reduction of q numerator + mask sum ----
    *reinterpret_cast<float2*>(xb + warp * XST + d0) = make_float2(qn0, qn1);
    if (lane == 0) xb[warp * XST + 64] = msl;
    __syncthreads();
    if (tid < 64) {
        float a = 0.f;
        #pragma unroll 8
        for (int w = 0; w < 32; ++w) a += xb[w * XST + tid];
        qn[tid] = a;
    } else if (tid == 64) {
        float a = 0.f;
        for (int w = 0; w < 32; ++w) a += xb[w * XST + 64];
        *msp = a;
    }
    __syncthreads();
    if (tid < 64) {   // q = (q_avg @ Wq) * C^-0.5
        const float inv = 1.f / (*msp + 1e-10f);
        float a = 0.f;
        #pragma unroll 8
        for (int d = 0; d < 64; ++d) a = fmaf(qn[d] * inv, Wq[d * 64 + tid], a);
        qsv[tid] = a * 0.35355339059327373f;
    }
    __syncthreads();

    // ================= softmax over s + o = sum(w*v), 4 warps per head ========
    {
        const int h = warp >> 2;
        const int p = ((warp & 3) << 5) | lane;  // 0..127 within head group
        float qh[8];
        #pragma unroll
        for (int c = 0; c < 8; ++c) qh[c] = qsv[h * 8 + c];
        float lg[16];
        float mx = -3.4e38f;
        #pragma unroll
        for (int i = 0; i < 16; ++i) {
            const int s = p + i * 128;
            float a = 1e9f * (mkb[s] - 1.f);
            #pragma unroll
            for (int c = 0; c < 8; ++c) a = fmaf(qh[c], kvT[c * S_LEN + s], a);
            lg[i] = a;
            mx = fmaxf(mx, a);
        }
        #pragma unroll
        for (int o = 16; o > 0; o >>= 1) mx = fmaxf(mx, __shfl_xor_sync(0xffffffffu, mx, o));
        if (lane == 0) red[warp] = mx;
        __syncthreads();
        const float gmx = fmaxf(fmaxf(red[h * 4], red[h * 4 + 1]),
                                fmaxf(red[h * 4 + 2], red[h * 4 + 3]));
        float sw = 0.f;
        float oc[8];
        #pragma unroll
        for (int c = 0; c < 8; ++c) oc[c] = 0.f;
        #pragma unroll
        for (int i = 0; i < 16; ++i) {
            const int s = p + i * 128;
            const float w = __expf(lg[i] - gmx);
            sw += w;
            #pragma unroll
            for (int c = 0; c < 8; ++c) oc[c] = fmaf(w, kvT[(8 + c) * S_LEN + s], oc[c]);
        }
        #pragma unroll
        for (int o = 16; o > 0; o >>= 1) {
            sw += __shfl_xor_sync(0xffffffffu, sw, o);
            #pragma unroll
            for (int c = 0; c < 8; ++c) oc[c] += __shfl_xor_sync(0xffffffffu, oc[c], o);
        }
        if (lane == 0) {
            float* rb = red + 32 + warp * 9;
            rb[0] = sw;
            #pragma unroll
            for (int c = 0; c < 8; ++c) rb[1 + c] = oc[c];
        }
        __syncthreads();
        if (tid < 64) {
            const int hh = tid >> 3, cc = tid & 7;
            float ssum = 0.f, osum = 0.f;
            #pragma unroll
            for (int w = 0; w < 4; ++w) {
                const float* rb = red + 32 + (hh * 4 + w) * 9;
                ssum += rb[0];
                osum += rb[1 + cc];
            }
            osv[tid] = osum / ssum;
        }
        __syncthreads();
    }

    // fold o into Wo:  Wop[j][d] = o[j] * Wo[j][d]
    for (int i = tid; i < 64 * 64; i += NTHR) wop[i] = osv[i >> 6] * Wo[i];
    __syncthreads();

    // ================= PASS 2: gate + output projection + residual ===========
    for (int t = 0; t < NTILES; ++t) {
        #pragma unroll
        for (int k = 0; k < 4; ++k) {
            const int sl = warp + 32 * k;
            const int s  = t * TILE + sl;
            const float2 xin = *reinterpret_cast<const float2*>(
                M_raw + ((size_t)s * R_LEN + r) * DDIM + d0);
            float sum = xin.x + xin.y;
            float sq  = xin.x * xin.x + xin.y * xin.y;
            #pragma unroll
            for (int o = 16; o > 0; o >>= 1) {
                sum += __shfl_xor_sync(0xffffffffu, sum, o);
                sq  += __shfl_xor_sync(0xffffffffu, sq, o);
            }
            const float mu  = sum * (1.f / 64.f);
            const float var = fmaf(-mu, mu, sq * (1.f / 64.f));
            const float inv = rsqrtf(var + 1e-5f);
            const float xh0 = fmaf((xin.x - mu) * inv, lng[d0],     lnbs[d0]);
            const float xh1 = fmaf((xin.y - mu) * inv, lng[d0 + 1], lnbs[d0 + 1]);
            *reinterpret_cast<float2*>(xb + sl * XST + d0)   = make_float2(xh0, xh1);
            *reinterpret_cast<float2*>(rawb + sl * XST + d0) = xin;
        }
        __syncthreads();

        const int sl = tid >> 3, jg = tid & 7;
        const int s  = t * TILE + sl;

        // GEMM1: Gpre = X @ Wg   (8 outputs per thread)
        unsigned long long a0 = 0ull, a1 = 0ull, a2 = 0ull, a3 = 0ull;
        {
            const float* xr = xb + sl * XST;
            const float* wr = wgs + jg * 8;
            #pragma unroll 4
            for (int d = 0; d < 64; ++d) {
                const unsigned long long xx = pk2(xr[d], xr[d]);
                const unsigned long long* w =
                    reinterpret_cast<const unsigned long long*>(wr + d * 64);
                a0 = fma2(xx, w[0], a0);
                a1 = fma2(xx, w[1], a1);
                a2 = fma2(xx, w[2], a2);
                a3 = fma2(xx, w[3], a3);
            }
        }
        float g[8];
        {
            const float2 b0 = up2(a0), b1 = up2(a1), b2 = up2(a2), b3 = up2(a3);
            const float* bgp = bgs + jg * 8;
            g[0] = b0.x + bgp[0]; g[1] = b0.y + bgp[1];
            g[2] = b1.x + bgp[2]; g[3] = b1.y + bgp[3];
            g[4] = b2.x + bgp[4]; g[5] = b2.y + bgp[5];
            g[6] = b3.x + bgp[6]; g[7] = b3.y + bgp[7];
            #pragma unroll
            for (int j = 0; j < 8; ++j) g[j] = __fdividef(1.f, 1.f + __expf(-g[j]));
        }
        __syncthreads();          // everyone done reading X
        #pragma unroll
        for (int j = 0; j < 4; ++j)
            *reinterpret_cast<float2*>(xb + sl * XST + jg * 8 + 2 * j) =
                make_float2(g[2 * j], g[2 * j + 1]);
        __syncthreads();

        // GEMM2: out = G @ Wop + bo + raw
        a0 = a1 = a2 = a3 = 0ull;
        {
            const float* gr = xb + sl * XST;
            const float* wr = wop + jg * 8;
            #pragma unroll 4
            for (int j = 0; j < 64; ++j) {
                const unsigned long long gg = pk2(gr[j], gr[j]);
                const unsigned long long* w =
                    reinterpret_cast<const unsigned long long*>(wr + j * 64);
                a0 = fma2(gg, w[0], a0);
                a1 = fma2(gg, w[1], a1);
                a2 = fma2(gg, w[2], a2);
                a3 = fma2(gg, w[3], a3);
            }
        }
        {
            const float2 b0 = up2(a0), b1 = up2(a1), b2 = up2(a2), b3 = up2(a3);
            const float* rr = rawb + sl * XST + jg * 8;
            const float* bp = bos + jg * 8;
            float4 o1, o2;
            o1.x = b0.x + bp[0] + rr[0];
            o1.y = b0.y + bp[1] + rr[1];
            o1.z = b1.x + bp[2] + rr[2];
            o1.w = b1.y + bp[3] + rr[3];
            o2.x = b2.x + bp[4] + rr[4];
            o2.y = b2.y + bp[5] + rr[5];
            o2.z = b3.x + bp[6] + rr[6];
            o2.w = b3.y + bp[7] + rr[7];
            float4* op = reinterpret_cast<float4*>(
                outp + ((size_t)s * R_LEN + r) * DDIM + jg * 8);
            op[0] = o1;
            op[1] = o2;
        }
        __syncthreads();
    }
}

extern "C" void kernel_launch(void* const* d_in, const int* in_sizes, int n_in,
                              void* d_out, int out_size) {
    const float* M_raw  = (const float*)d_in[0];
    const float* M_mask = (const float*)d_in[1];
    const float* ln_g   = (const float*)d_in[2];
    const float* ln_b   = (const float*)d_in[3];
    const float* Wq     = (const float*)d_in[4];
    const float* Wk     = (const float*)d_in[5];
    const float* Wv     = (const float*)d_in[6];
    const float* Wg     = (const float*)d_in[7];
    const float* bg     = (const float*)d_in[8];
    const float* Wo     = (const float*)d_in[9];
    const float* bo     = (const float*)d_in[10];
    float* outp = (float*)d_out;

    cudaFuncSetAttribute(msa_col_attn, cudaFuncAttributeMaxDynamicSharedMemorySize,
                         (int)SMEM_BYTES);
    msa_col_attn<<<R_LEN, NTHR, SMEM_BYTES>>>(M_raw, M_mask, ln_g, ln_b, Wq, Wk, Wv,
                                              Wg, bg, Wo, bo, outp);
}

// round 2
// speedup vs baseline: 1.6072x; 1.6072x over previous
#include <cuda_runtime.h>

// MSAColumnGlobalAttention, B=1 S=2048 R=384 D=64 H=8 C=8
// One CTA per residue r. Two passes over the sequence axis with LN recompute.
// Round 2: bank-perfect interleaved weight layouts + 2-row register blocking.

namespace {
constexpr int S_LEN  = 2048;
constexpr int R_LEN  = 384;
constexpr int DDIM   = 64;
constexpr int TILE1  = 128;             // pass-1 tile rows
constexpr int NT1    = S_LEN / TILE1;   // 16
constexpr int TILE2  = 256;             // pass-2 block rows
constexpr int NT2    = S_LEN / TILE2;   // 8
constexpr int NTHR   = 1024;

constexpr int ST_KV  = 2052;            // kvT row stride (conflict-free stores)
constexpr int XST1   = 66;              // pass-1 x stage stride
constexpr int XST2   = 68;              // pass-2 x/gate stage stride

// shared-memory layout (float offsets)
constexpr int OFF_KVT  = 0;                       // kvT[16][2052]; pass-2 xb2[256][68] aliases
constexpr int OFF_XB1  = OFF_KVT + 16 * ST_KV;    // 32832: xb1[128][66]
constexpr int OFF_MASK = OFF_XB1 + TILE1 * XST1;  // mask[2048]
constexpr int OFF_WKVI = OFF_MASK + S_LEN;        // wkvi[32][8][4] = 1024
constexpr int OFF_WGI  = OFF_WKVI + 1024;         // wgi[32][32][4] = 4096
constexpr int OFF_WOI  = OFF_WGI + 4096;          // woi (o-folded Wo, interleaved) 4096
constexpr int OFF_LNG  = OFF_WOI + 4096;
constexpr int OFF_LNB  = OFF_LNG + 64;
constexpr int OFF_BG   = OFF_LNB + 64;
constexpr int OFF_BO   = OFF_BG + 64;
constexpr int OFF_QN   = OFF_BO + 64;
constexpr int OFF_QS   = OFF_QN + 64;
constexpr int OFF_OSV  = OFF_QS + 64;
constexpr int OFF_RED  = OFF_OSV + 64;            // softmax scratch [320]
constexpr int OFF_MS   = OFF_RED + 320;
constexpr int SMEM_FLOATS = OFF_MS + 4;
constexpr size_t SMEM_BYTES = (size_t)SMEM_FLOATS * sizeof(float);
}  // namespace

__device__ __forceinline__ unsigned long long pk2(float x, float y) {
    unsigned long long r;
    asm("mov.b64 %0,{%1,%2};" : "=l"(r) : "f"(x), "f"(y));
    return r;
}
__device__ __forceinline__ float2 up2(unsigned long long a) {
    float2 r;
    asm("mov.b64 {%0,%1},%2;" : "=f"(r.x), "=f"(r.y) : "l"(a));
    return r;
}
__device__ __forceinline__ unsigned long long fma2(unsigned long long a,
                                                   unsigned long long b,
                                                   unsigned long long c) {
    unsigned long long d;
    asm("fma.rn.f32x2 %0,%1,%2,%3;" : "=l"(d) : "l"(a), "l"(b), "l"(c));
    return d;
}
__device__ __forceinline__ float sigf(float v) {
    return __fdividef(1.f, 1.f + __expf(-v));
}

__global__ __launch_bounds__(NTHR, 1)
void msa_col_attn(const float* __restrict__ M_raw, const float* __restrict__ M_mask,
                  const float* __restrict__ ln_g, const float* __restrict__ ln_b,
                  const float* __restrict__ Wq, const float* __restrict__ Wk,
                  const float* __restrict__ Wv, const float* __restrict__ Wg,
                  const float* __restrict__ bg, const float* __restrict__ Wo,
                  const float* __restrict__ bo, float* __restrict__ outp)
{
    extern __shared__ float sm[];
    float* kvT  = sm + OFF_KVT;
    float* xb2  = sm + OFF_KVT;    // alias: pass-2 stage (kvT dead then)
    float* xb1  = sm + OFF_XB1;
    float* mkb  = sm + OFF_MASK;
    float* wkvi = sm + OFF_WKVI;
    float* wgi  = sm + OFF_WGI;
    float* woi  = sm + OFF_WOI;
    float* lng  = sm + OFF_LNG;
    float* lnbs = sm + OFF_LNB;
    float* bgs  = sm + OFF_BG;
    float* bos  = sm + OFF_BO;
    float* qn   = sm + OFF_QN;
    float* qsv  = sm + OFF_QS;
    float* osv  = sm + OFF_OSV;
    float* red  = sm + OFF_RED;
    float* msp  = sm + OFF_MS;

    const int r    = blockIdx.x;
    const int tid  = threadIdx.x;
    const int lane = tid & 31;
    const int warp = tid >> 5;
    const int d0   = lane << 1;

    // ---- stage weights (interleaved bank-perfect layouts) ----
    // wgi[d2*128 + cp*4 + q] = Wg[(2*d2 + (q>>1))*64 + 2*cp + (q&1)]
    for (int i = tid; i < 4096; i += NTHR) {
        const int dd2 = i >> 7, rem = i & 127, cp = rem >> 2, q = rem & 3;
        wgi[i] = Wg[(2 * dd2 + (q >> 1)) * 64 + 2 * cp + (q & 1)];
    }
    // wkvi[d2*32 + cg*4 + q], cols 0..7 = Wk, 8..15 = Wv
    for (int i = tid; i < 1024; i += NTHR) {
        const int dd2 = i >> 5, rem = i & 31, cg = rem >> 2, q = rem & 3;
        const int d = 2 * dd2 + (q >> 1), c = 2 * cg + (q & 1);
        wkvi[i] = (c < 8) ? Wk[d * 8 + c] : Wv[d * 8 + (c - 8)];
    }
    if (tid < 64) {
        lng[tid] = ln_g[tid]; lnbs[tid] = ln_b[tid];
        bgs[tid] = bg[tid];   bos[tid]  = bo[tid];
    }
    __syncthreads();

    // ================= PASS 1: LN, k/v, masked q accumulation =================
    float qn0 = 0.f, qn1 = 0.f, msl = 0.f;

    for (int t = 0; t < NT1; ++t) {
        #pragma unroll
        for (int k = 0; k < 4; ++k) {
            const int sl = warp + 32 * k;           // 0..127
            const int s  = t * TILE1 + sl;
            const float2 xin = *reinterpret_cast<const float2*>(
                M_raw + ((size_t)s * R_LEN + r) * DDIM + d0);
            float sum = xin.x + xin.y;
            float sq  = xin.x * xin.x + xin.y * xin.y;
            #pragma unroll
            for (int o = 16; o > 0; o >>= 1) {
                sum += __shfl_xor_sync(0xffffffffu, sum, o);
                sq  += __shfl_xor_sync(0xffffffffu, sq, o);
            }
            const float mu  = sum * (1.f / 64.f);
            const float var = fmaf(-mu, mu, sq * (1.f / 64.f));
            const float inv = rsqrtf(var + 1e-5f);
            const float xh0 = fmaf((xin.x - mu) * inv, lng[d0],     lnbs[d0]);
            const float xh1 = fmaf((xin.y - mu) * inv, lng[d0 + 1], lnbs[d0 + 1]);
            float m = (lane == 0) ? M_mask[(size_t)s * R_LEN + r] : 0.f;
            m = __shfl_sync(0xffffffffu, m, 0);
            if (lane == 0) { mkb[s] = m; msl += m; }
            qn0 = fmaf(m, xh0, qn0);
            qn1 = fmaf(m, xh1, qn1);
            *reinterpret_cast<float2*>(xb1 + sl * XST1 + d0) = make_float2(xh0, xh1);
        }
        __syncthreads();
        if (tid < 512) {   // k/v GEMM: 2 rows x 1 colpair per thread
            const int rp = tid >> 3, cg = tid & 7;
            const float* x0 = xb1 + (2 * rp) * XST1;
            const float* x1 = x0 + XST1;
            unsigned long long a = 0ull, b = 0ull;
            #pragma unroll 8
            for (int dd2 = 0; dd2 < 32; ++dd2) {
                const float2 xv0 = *reinterpret_cast<const float2*>(x0 + 2 * dd2);
                const float2 xv1 = *reinterpret_cast<const float2*>(x1 + 2 * dd2);
                const ulonglong2 w = *reinterpret_cast<const ulonglong2*>(
                    wkvi + dd2 * 32 + cg * 4);
                a = fma2(pk2(xv0.x, xv0.x), w.x, a);
                a = fma2(pk2(xv0.y, xv0.y), w.y, a);
                b = fma2(pk2(xv1.x, xv1.x), w.x, b);
                b = fma2(pk2(xv1.y, xv1.y), w.y, b);
            }
            const int s = t * TILE1 + 2 * rp;
            const float2 av = up2(a), bv = up2(b);
            kvT[(2 * cg) * ST_KV + s]         = av.x;
            kvT[(2 * cg + 1) * ST_KV + s]     = av.y;
            kvT[(2 * cg) * ST_KV + s + 1]     = bv.x;
            kvT[(2 * cg + 1) * ST_KV + s + 1] = bv.y;
        }
        __syncthreads();
    }

    // ---- deterministic cross-warp reduction of q numerator + mask sum ----
    *reinterpret_cast<float2*>(xb1 + warp * XST1 + d0) = make_float2(qn0, qn1);
    if (lane == 0) xb1[warp * XST1 + 64] = msl;
    __syncthreads();
    if (tid < 64) {
        float a = 0.f;
        #pragma unroll 8
        for (int w = 0; w < 32; ++w) a += xb1[w * XST1 + tid];
        qn[tid] = a;
    } else if (tid == 64) {
        float a = 0.f;
        for (int w = 0; w < 32; ++w) a += xb1[w * XST1 + 64];
        *msp = a;
    }
    __syncthreads();
    if (tid < 64) {   // q = (q_avg @ Wq) * C^-0.5
        const float inv = 1.f / (*msp + 1e-10f);
        float a = 0.f;
        #pragma unroll 8
        for (int d = 0; d < 64; ++d) a = fmaf(qn[d] * inv, Wq[d * 64 + tid], a);
        qsv[tid] = a * 0.35355339059327373f;
    }
    __syncthreads();

    // ================= softmax over s + o = sum(w*v), 4 warps per head ========
    {
        const int h = warp >> 2;
        const int p = ((warp & 3) << 5) | lane;  // 0..127 within head group
        float qh[8];
        #pragma unroll
        for (int c = 0; c < 8; ++c) qh[c] = qsv[h * 8 + c];
        float lg[16];
        float mx = -3.4e38f;
        #pragma unroll
        for (int i = 0; i < 16; ++i) {
            const int s = p + i * 128;
            float a = 1e9f * (mkb[s] - 1.f);
            #pragma unroll
            for (int c = 0; c < 8; ++c) a = fmaf(qh[c], kvT[c * ST_KV + s], a);
            lg[i] = a;
            mx = fmaxf(mx, a);
        }
        #pragma unroll
        for (int o = 16; o > 0; o >>= 1) mx = fmaxf(mx, __shfl_xor_sync(0xffffffffu, mx, o));
        if (lane == 0) red[warp] = mx;
        __syncthreads();
        const float gmx = fmaxf(fmaxf(red[h * 4], red[h * 4 + 1]),
                                fmaxf(red[h * 4 + 2], red[h * 4 + 3]));
        float sw = 0.f;
        float oc[8];
        #pragma unroll
        for (int c = 0; c < 8; ++c) oc[c] = 0.f;
        #pragma unroll
        for (int i = 0; i < 16; ++i) {
            const int s = p + i * 128;
            const float w = __expf(lg[i] - gmx);
            sw += w;
            #pragma unroll
            for (int c = 0; c < 8; ++c) oc[c] = fmaf(w, kvT[(8 + c) * ST_KV + s], oc[c]);
        }
        #pragma unroll
        for (int o = 16; o > 0; o >>= 1) {
            sw += __shfl_xor_sync(0xffffffffu, sw, o);
            #pragma unroll
            for (int c = 0; c < 8; ++c) oc[c] += __shfl_xor_sync(0xffffffffu, oc[c], o);
        }
        if (lane == 0) {
            float* rb = red + 32 + warp * 9;
            rb[0] = sw;
            #pragma unroll
            for (int c = 0; c < 8; ++c) rb[1 + c] = oc[c];
        }
        __syncthreads();
        if (tid < 64) {
            const int hh = tid >> 3, cc = tid & 7;
            float ssum = 0.f, osum = 0.f;
            #pragma unroll
            for (int w = 0; w < 4; ++w) {
                const float* rb = red + 32 + (hh * 4 + w) * 9;
                ssum += rb[0];
                osum += rb[1 + cc];
            }
            osv[tid] = osum / ssum;
        }
        __syncthreads();
    }

    // fold o into Wo, interleaved layout:
    // woi[d2*128 + cp*4 + q] = osv[j] * Wo[j*64 + col], j=2*d2+(q>>1), col=2*cp+(q&1)
    for (int i = tid; i < 4096; i += NTHR) {
        const int dd2 = i >> 7, rem = i & 127, cp = rem >> 2, q = rem & 3;
        const int j = 2 * dd2 + (q >> 1), col = 2 * cp + (q & 1);
        woi[i] = osv[j] * Wo[j * 64 + col];
    }
    __syncthreads();   // also: kvT fully dead past here -> xb2 alias live

    // ================= PASS 2: gate + output projection + residual ===========
    const int rp = tid >> 3, jg = tid & 7;   // rows 2rp,2rp+1; colpairs jg+8k

    for (int t = 0; t < NT2; ++t) {
        // ---- LN 256 rows (8 per warp) ----
        #pragma unroll
        for (int k = 0; k < 8; ++k) {
            const int sl = warp + 32 * k;           // 0..255
            const int s  = t * TILE2 + sl;
            const float2 xin = *reinterpret_cast<const float2*>(
                M_raw + ((size_t)s * R_LEN + r) * DDIM + d0);
            float sum = xin.x + xin.y;
            float sq  = xin.x * xin.x + xin.y * xin.y;
            #pragma unroll
            for (int o = 16; o > 0; o >>= 1) {
                sum += __shfl_xor_sync(0xffffffffu, sum, o);
                sq  += __shfl_xor_sync(0xffffffffu, sq, o);
            }
            const float mu  = sum * (1.f / 64.f);
            const float var = fmaf(-mu, mu, sq * (1.f / 64.f));
            const float inv = rsqrtf(var + 1e-5f);
            const float xh0 = fmaf((xin.x - mu) * inv, lng[d0],     lnbs[d0]);
            const float xh1 = fmaf((xin.y - mu) * inv, lng[d0 + 1], lnbs[d0 + 1]);
            *reinterpret_cast<float2*>(xb2 + sl * XST2 + d0) = make_float2(xh0, xh1);
        }
        __syncthreads();

        const float* x0 = xb2 + (2 * rp) * XST2;
        const float* x1 = x0 + XST2;

        // ---- GEMM1: Gpre = X @ Wg (2 rows x 4 colpairs per thread) ----
        unsigned long long a[4], b[4];
        #pragma unroll
        for (int k = 0; k < 4; ++k) { a[k] = 0ull; b[k] = 0ull; }
        #pragma unroll 8
        for (int dd2 = 0; dd2 < 32; ++dd2) {
            const float2 xv0 = *reinterpret_cast<const float2*>(x0 + 2 * dd2);
            const float2 xv1 = *reinterpret_cast<const float2*>(x1 + 2 * dd2);
            const unsigned long long xa0 = pk2(xv0.x, xv0.x);
            const unsigned long long xb0 = pk2(xv0.y, xv0.y);
            const unsigned long long xa1 = pk2(xv1.x, xv1.x);
            const unsigned long long xb1v = pk2(xv1.y, xv1.y);
            #pragma unroll
            for (int k = 0; k < 4; ++k) {
                const ulonglong2 w = *reinterpret_cast<const ulonglong2*>(
                    wgi + dd2 * 128 + (jg + 8 * k) * 4);
                a[k] = fma2(xa0, w.x, a[k]);
                a[k] = fma2(xb0, w.y, a[k]);
                b[k] = fma2(xa1, w.x, b[k]);
                b[k] = fma2(xb1v, w.y, b[k]);
            }
        }
        __syncthreads();   // everyone done reading xh

        // sigmoid gates -> store into xb2 (overwrite xh)
        #pragma unroll
        for (int k = 0; k < 4; ++k) {
            const int cp = jg + 8 * k;
            const float2 bgv = *reinterpret_cast<const float2*>(bgs + 2 * cp);
            const float2 av = up2(a[k]), bv = up2(b[k]);
            *reinterpret_cast<float2*>(xb2 + (2 * rp) * XST2 + 2 * cp) =
                make_float2(sigf(av.x + bgv.x), sigf(av.y + bgv.y));
            *reinterpret_cast<float2*>(xb2 + (2 * rp + 1) * XST2 + 2 * cp) =
                make_float2(sigf(bv.x + bgv.x), sigf(bv.y + bgv.y));
        }
        __syncthreads();

        // prefetch raw residual (L2-hot: same rows read in LN just above)
        const int s0 = t * TILE2 + 2 * rp;
        const float* rbase0 = M_raw + ((size_t)s0 * R_LEN + r) * DDIM;
        const float* rbase1 = rbase0 + (size_t)R_LEN * DDIM;
        float2 rw0[4], rw1[4];
        #pragma unroll
        for (int k = 0; k < 4; ++k) {
            rw0[k] = *reinterpret_cast<const float2*>(rbase0 + 2 * (jg + 8 * k));
            rw1[k] = *reinterpret_cast<const float2*>(rbase1 + 2 * (jg + 8 * k));
        }

        // ---- GEMM2: out = G @ (o.Wo) + bo + raw ----
        #pragma unroll
        for (int k = 0; k < 4; ++k) { a[k] = 0ull; b[k] = 0ull; }
        #pragma unroll 8
        for (int j2 = 0; j2 < 32; ++j2) {
            const float2 gv0 = *reinterpret_cast<const float2*>(x0 + 2 * j2);
            const float2 gv1 = *reinterpret_cast<const float2*>(x1 + 2 * j2);
            const unsigned long long ga0 = pk2(gv0.x, gv0.x);
            const unsigned long long gb0 = pk2(gv0.y, gv0.y);
            const unsigned long long ga1 = pk2(gv1.x, gv1.x);
            const unsigned long long gb1 = pk2(gv1.y, gv1.y);
            #pragma unroll
            for (int k = 0; k < 4; ++k) {
                const ulonglong2 w = *reinterpret_cast<const ulonglong2*>(
                    woi + j2 * 128 + (jg + 8 * k) * 4);
                a[k] = fma2(ga0, w.x, a[k]);
                a[k] = fma2(gb0, w.y, a[k]);
                b[k] = fma2(ga1, w.x, b[k]);
                b[k] = fma2(gb1, w.y, b[k]);
            }
        }
        {
            float* obase0 = outp + ((size_t)s0 * R_LEN + r) * DDIM;
            float* obase1 = obase0 + (size_t)R_LEN * DDIM;
            #pragma unroll
            for (int k = 0; k < 4; ++k) {
                const int cp = jg + 8 * k;
                const float2 bov = *reinterpret_cast<const float2*>(bos + 2 * cp);
                const float2 av = up2(a[k]), bv = up2(b[k]);
                *reinterpret_cast<float2*>(obase0 + 2 * cp) =
                    make_float2(av.x + bov.x + rw0[k].x, av.y + bov.y + rw0[k].y);
                *reinterpret_cast<float2*>(obase1 + 2 * cp) =
                    make_float2(bv.x + bov.x + rw1[k].x, bv.y + bov.y + rw1[k].y);
            }
        }
        __syncthreads();   // before next block overwrites xb2
    }
}

extern "C" void kernel_launch(void* const* d_in, const int* in_sizes, int n_in,
                              void* d_out, int out_size) {
    const float* M_raw  = (const float*)d_in[0];
    const float* M_mask = (const float*)d_in[1];
    const float* ln_g   = (const float*)d_in[2];
    const float* ln_b   = (const float*)d_in[3];
    const float* Wq     = (const float*)d_in[4];
    const float* Wk     = (const float*)d_in[5];
    const float* Wv     = (const float*)d_in[6];
    const float* Wg     = (const float*)d_in[7];
    const float* bg     = (const float*)d_in[8];
    const float* Wo     = (const float*)d_in[9];
    const float* bo     = (const float*)d_in[10];
    float* outp = (float*)d_out;

    cudaFuncSetAttribute(msa_col_attn, cudaFuncAttributeMaxDynamicSharedMemorySize,
                         (int)SMEM_BYTES);
    msa_col_attn<<<R_LEN, NTHR, SMEM_BYTES>>>(M_raw, M_mask, ln_g, ln_b, Wq, Wk, Wv,
                                              Wg, bg, Wo, bo, outp);
}